// round 13
// baseline (speedup 1.0000x reference)
#include <cuda_runtime.h>
#include <cuda_fp16.h>
#include <math.h>

#define NN 50000
#define EE 1600000
#define BB 4
#define FF 16
#define HH 16
#define BF 64   // BB*FF halves per node row (128 B)
#define CC 10
#define CAP 96  // padded CSR bucket size (Poisson(32) tail @96 ~ 1e-18/node)

// ---------------- device scratch (static: no allocation allowed) ----------
__device__ uint4 g_bufA[NN * 8];    // z   (unscaled, layer input)
__device__ uint4 g_bufAs[NN * 8];   // z_s (dinv-scaled)
__device__ uint4 g_bufB[NN * 8];
__device__ uint4 g_bufBs[NN * 8];
__device__ uint4 g_t1[NN * 8];      // scaled-domain prop outputs
__device__ uint4 g_t2[NN * 8];
__device__ unsigned short g_csr[NN * CAP]; // bucket n at n*CAP: src only (u16)
__device__ int   g_wp[NN];          // bucket fill = in-degree
__device__ int   g_deg[NN];         // out-degree
__device__ float g_dinv[NN];
__device__ float g_dinv2[NN];       // dinv^2 (prop epilogue scale)
__device__ float g_rdinv[NN];       // sqrt(deg) (dense un-scale)
__device__ float g_pool[BF];

__device__ __forceinline__ float elu1(float x) {
    return x > 0.0f ? x : expm1f(x);
}

// ---------------- transpose x [B,F,N] fp32 -> [N, 64] fp16 + init ----------
__global__ void k_transpose(const float* __restrict__ x, __half* __restrict__ dst) {
    int flat = (blockIdx.y * gridDim.x + blockIdx.x) * 256 + threadIdx.y * 32 + threadIdx.x;
    if (flat < NN) { g_wp[flat] = 0; g_deg[flat] = 0; }

    __shared__ float tile[32][33];
    int n0 = blockIdx.x * 32;
    int bf0 = blockIdx.y * 32;
    int tx = threadIdx.x;          // 32
    int ty = threadIdx.y;          // 8
    #pragma unroll
    for (int i = ty; i < 32; i += 8) {
        int n = n0 + tx;
        tile[i][tx] = (n < NN) ? x[(bf0 + i) * NN + n] : 0.0f;
    }
    __syncthreads();
    #pragma unroll
    for (int i = ty; i < 32; i += 8) {
        int n = n0 + i;
        if (n < NN) dst[n * BF + bf0 + tx] = __float2half_rn(tile[tx][i]);
    }
}

// ---------------- fused: deg RED + bucket scatter (1 edge/thread) ---------
__global__ void k_fuse(const int* __restrict__ ei) {
    int e = blockIdx.x * 256 + threadIdx.x;
    if (e >= EE) return;
    int s = ei[e];
    int d = ei[EE + e];
    atomicAdd(&g_deg[s], 1);
    int pos = atomicAdd(&g_wp[d], 1);
    g_csr[d * CAP + pos] = (unsigned short)s;
}

// ---------------- dinv/dinv2/rdinv + produce scaled input buffer -----------
__global__ void k_dinvscale(const uint4* __restrict__ z, uint4* __restrict__ zs) {
    int t = blockIdx.x * 256 + threadIdx.x;
    if (t < BF) g_pool[t] = 0.0f;
    if (t >= NN * 8) return;
    int n = t >> 3;
    int c = t & 7;
    int d = g_deg[n];
    float di = (d > 0) ? rsqrtf((float)d) : 0.0f;
    if (c == 0) {
        g_dinv[n] = di;
        g_dinv2[n] = di * di;
        g_rdinv[n] = (d > 0) ? sqrtf((float)d) : 0.0f;
    }
    __half2 dh = __float2half2_rn(di);
    uint4 v = z[t];
    __half2 h0 = __hmul2(dh, *(__half2*)&v.x);
    __half2 h1 = __hmul2(dh, *(__half2*)&v.y);
    __half2 h2 = __hmul2(dh, *(__half2*)&v.z);
    __half2 h3 = __hmul2(dh, *(__half2*)&v.w);
    uint4 r;
    r.x = *(unsigned*)&h0; r.y = *(unsigned*)&h1;
    r.z = *(unsigned*)&h2; r.w = *(unsigned*)&h3;
    zs[t] = r;
}

// ---------------- sparse prop, scaled domain: weight-free row sums ---------
// out_s[n,:] = -dinv2[n] * sum_{e->n} in_s[src_e,:]
// warp per dst node; 4 groups x 8 lanes; 16 edges per main-loop iteration
// with 4 independent row loads in flight and 4 accumulator banks.
__global__ void __launch_bounds__(256, 4) k_prop(const __half* __restrict__ in,
                                                 __half* __restrict__ out) {
    int w = (blockIdx.x * 256 + threadIdx.x) >> 5;
    int lane = threadIdx.x & 31;
    if (w >= NN) return;
    int g = lane >> 3;             // edge-group 0..3
    int q = lane & 7;              // 16B slice 0..7
    const char* base = (const char*)in + q * 16;
    int len = g_wp[w];
    int full = len >> 2;           // unconditional 4-edge steps
    int rem = len & 3;             // groups g < rem take one tail edge

    const __half2 z2 = __float2half2_rn(0.0f);
    __half2 A0 = z2, A1 = z2, A2 = z2, A3 = z2;
    __half2 B0 = z2, B1 = z2, B2 = z2, B3 = z2;
    __half2 C0 = z2, C1 = z2, C2 = z2, C3 = z2;
    __half2 D0 = z2, D1 = z2, D2 = z2, D3 = z2;

    int j = w * CAP + g;
    int k = 0;
    // 16 edges / iteration: 4 idx loads then 4 row loads, all independent
    for (; k + 4 <= full; k += 4, j += 16) {
        unsigned s0 = __ldg(&g_csr[j]);
        unsigned s1 = __ldg(&g_csr[j + 4]);
        unsigned s2 = __ldg(&g_csr[j + 8]);
        unsigned s3 = __ldg(&g_csr[j + 12]);
        uint4 v0 = *(const uint4*)(base + s0 * 128);
        uint4 v1 = *(const uint4*)(base + s1 * 128);
        uint4 v2 = *(const uint4*)(base + s2 * 128);
        uint4 v3 = *(const uint4*)(base + s3 * 128);
        A0 = __hadd2(A0, *(__half2*)&v0.x);
        A1 = __hadd2(A1, *(__half2*)&v0.y);
        A2 = __hadd2(A2, *(__half2*)&v0.z);
        A3 = __hadd2(A3, *(__half2*)&v0.w);
        B0 = __hadd2(B0, *(__half2*)&v1.x);
        B1 = __hadd2(B1, *(__half2*)&v1.y);
        B2 = __hadd2(B2, *(__half2*)&v1.z);
        B3 = __hadd2(B3, *(__half2*)&v1.w);
        C0 = __hadd2(C0, *(__half2*)&v2.x);
        C1 = __hadd2(C1, *(__half2*)&v2.y);
        C2 = __hadd2(C2, *(__half2*)&v2.z);
        C3 = __hadd2(C3, *(__half2*)&v2.w);
        D0 = __hadd2(D0, *(__half2*)&v3.x);
        D1 = __hadd2(D1, *(__half2*)&v3.y);
        D2 = __hadd2(D2, *(__half2*)&v3.z);
        D3 = __hadd2(D3, *(__half2*)&v3.w);
    }
    for (; k < full; k++, j += 4) {
        unsigned s0 = __ldg(&g_csr[j]);
        uint4 v = *(const uint4*)(base + s0 * 128);
        A0 = __hadd2(A0, *(__half2*)&v.x);
        A1 = __hadd2(A1, *(__half2*)&v.y);
        A2 = __hadd2(A2, *(__half2*)&v.z);
        A3 = __hadd2(A3, *(__half2*)&v.w);
    }
    if (g < rem) {
        unsigned s0 = __ldg(&g_csr[j]);
        uint4 v = *(const uint4*)(base + s0 * 128);
        B0 = __hadd2(B0, *(__half2*)&v.x);
        B1 = __hadd2(B1, *(__half2*)&v.y);
        B2 = __hadd2(B2, *(__half2*)&v.z);
        B3 = __hadd2(B3, *(__half2*)&v.w);
    }

    // combine banks, go fp32, reduce across the 4 groups
    float2 f0 = __half22float2(__hadd2(__hadd2(A0, B0), __hadd2(C0, D0)));
    float2 f1 = __half22float2(__hadd2(__hadd2(A1, B1), __hadd2(C1, D1)));
    float2 f2 = __half22float2(__hadd2(__hadd2(A2, B2), __hadd2(C2, D2)));
    float2 f3 = __half22float2(__hadd2(__hadd2(A3, B3), __hadd2(C3, D3)));
    float a0 = f0.x, a1 = f0.y, a2 = f1.x, a3 = f1.y;
    float a4 = f2.x, a5 = f2.y, a6 = f3.x, a7 = f3.y;

    a0 += __shfl_xor_sync(0xffffffffu, a0, 8);  a0 += __shfl_xor_sync(0xffffffffu, a0, 16);
    a1 += __shfl_xor_sync(0xffffffffu, a1, 8);  a1 += __shfl_xor_sync(0xffffffffu, a1, 16);
    a2 += __shfl_xor_sync(0xffffffffu, a2, 8);  a2 += __shfl_xor_sync(0xffffffffu, a2, 16);
    a3 += __shfl_xor_sync(0xffffffffu, a3, 8);  a3 += __shfl_xor_sync(0xffffffffu, a3, 16);
    a4 += __shfl_xor_sync(0xffffffffu, a4, 8);  a4 += __shfl_xor_sync(0xffffffffu, a4, 16);
    a5 += __shfl_xor_sync(0xffffffffu, a5, 8);  a5 += __shfl_xor_sync(0xffffffffu, a5, 16);
    a6 += __shfl_xor_sync(0xffffffffu, a6, 8);  a6 += __shfl_xor_sync(0xffffffffu, a6, 16);
    a7 += __shfl_xor_sync(0xffffffffu, a7, 8);  a7 += __shfl_xor_sync(0xffffffffu, a7, 16);

    if (g == 0) {
        float sc = -g_dinv2[w];
        __half2 h0 = __floats2half2_rn(sc * a0, sc * a1);
        __half2 h1 = __floats2half2_rn(sc * a2, sc * a3);
        __half2 h2 = __floats2half2_rn(sc * a4, sc * a5);
        __half2 h3 = __floats2half2_rn(sc * a6, sc * a7);
        uint4 r;
        r.x = *(unsigned*)&h0;
        r.y = *(unsigned*)&h1;
        r.z = *(unsigned*)&h2;
        r.w = *(unsigned*)&h3;
        *(uint4*)((char*)out + w * 128 + q * 16) = r;
    }
}

// ---------------- dense ----------------------------------------------------
// inputs: z (unscaled), t1_s, t2_s (scaled). un-scale with rdinv.
// outputs: h (unscaled) and, if WS, h_s = dinv*h for next layer's props.
__device__ __forceinline__ void unpack8(uint4 v, float* a) {
    float2 f;
    f = __half22float2(*(const __half2*)&v.x); a[0] = f.x; a[1] = f.y;
    f = __half22float2(*(const __half2*)&v.y); a[2] = f.x; a[3] = f.y;
    f = __half22float2(*(const __half2*)&v.z); a[4] = f.x; a[5] = f.y;
    f = __half22float2(*(const __half2*)&v.w); a[6] = f.x; a[7] = f.y;
}

template<int WS>
__global__ __launch_bounds__(256) void k_dense(const __half* __restrict__ z,
                                               const __half* __restrict__ t1s,
                                               const __half* __restrict__ t2s,
                                               const float* __restrict__ W,
                                               const float* __restrict__ bias,
                                               __half* __restrict__ out,
                                               __half* __restrict__ outs) {
    __shared__ float sW[48 * 16];  // sW[(k*16+f)*16 + o] = W[k][o][f]
    __shared__ float sB[16];
    int tid = threadIdx.x;
    for (int j = tid; j < 768; j += 256) {
        int kf = j >> 4;
        int o = j & 15;
        int k = kf >> 4;
        int f = kf & 15;
        sW[j] = W[k * 256 + o * 16 + f];
    }
    if (tid < 16) sB[tid] = bias[tid];
    __syncthreads();

    int r = blockIdx.x * 256 + tid;
    if (r >= NN * BB) return;
    int n = r >> 2;
    float rd = g_rdinv[n];

    float a[48];
    {
        const uint4* p0 = (const uint4*)(z + r * 16);
        const uint4* p1 = (const uint4*)(t1s + r * 16);
        const uint4* p2 = (const uint4*)(t2s + r * 16);
        unpack8(p0[0], a);      unpack8(p0[1], a + 8);
        unpack8(p1[0], a + 16); unpack8(p1[1], a + 24);
        unpack8(p2[0], a + 32); unpack8(p2[1], a + 40);
        float rd2 = 2.0f * rd;
        #pragma unroll
        for (int i = 0; i < 16; i++) {
            a[16 + i] *= rd;                               // t1 true
            a[32 + i] = fmaf(rd2, a[32 + i], -a[i]);       // 2*t2true - z
        }
    }
    float acc[16];
    #pragma unroll
    for (int o = 0; o < 16; o++) acc[o] = sB[o];
    #pragma unroll
    for (int kk = 0; kk < 48; kk++) {
        float av = a[kk];
        const float4* w4 = (const float4*)(sW + kk * 16);
        #pragma unroll
        for (int qq = 0; qq < 4; qq++) {
            float4 w = w4[qq];
            acc[qq * 4 + 0] = fmaf(av, w.x, acc[qq * 4 + 0]);
            acc[qq * 4 + 1] = fmaf(av, w.y, acc[qq * 4 + 1]);
            acc[qq * 4 + 2] = fmaf(av, w.z, acc[qq * 4 + 2]);
            acc[qq * 4 + 3] = fmaf(av, w.w, acc[qq * 4 + 3]);
        }
    }
    float h[16];
    #pragma unroll
    for (int i = 0; i < 16; i++) h[i] = elu1(acc[i]);

    uint4 o0, o1;
    {
        unsigned* po = (unsigned*)&o0;
        unsigned* po1 = (unsigned*)&o1;
        #pragma unroll
        for (int qq = 0; qq < 4; qq++) {
            __half2 hh = __floats2half2_rn(h[qq * 2 + 0], h[qq * 2 + 1]);
            po[qq] = *(unsigned*)&hh;
            __half2 hh2 = __floats2half2_rn(h[8 + qq * 2 + 0], h[8 + qq * 2 + 1]);
            po1[qq] = *(unsigned*)&hh2;
        }
    }
    uint4* dst = (uint4*)(out + r * 16);
    dst[0] = o0;
    dst[1] = o1;

    if (WS) {
        float di = g_dinv[n];
        uint4 s0, s1;
        unsigned* ps0 = (unsigned*)&s0;
        unsigned* ps1 = (unsigned*)&s1;
        #pragma unroll
        for (int qq = 0; qq < 4; qq++) {
            __half2 hh = __floats2half2_rn(di * h[qq * 2 + 0], di * h[qq * 2 + 1]);
            ps0[qq] = *(unsigned*)&hh;
            __half2 hh2 = __floats2half2_rn(di * h[8 + qq * 2 + 0], di * h[8 + qq * 2 + 1]);
            ps1[qq] = *(unsigned*)&hh2;
        }
        uint4* dsts = (uint4*)(outs + r * 16);
        dsts[0] = s0;
        dsts[1] = s1;
    }
}

// ---------------- mean pool over nodes (fp16 in, fp32 accum) ---------------
__global__ void k_pool(const __half2* __restrict__ h) {
    int tid = blockIdx.x * blockDim.x + threadIdx.x;
    int c = tid & 31;              // half2 column 0..31
    int grp = tid >> 5;
    int ngrp = (gridDim.x * blockDim.x) >> 5;
    float sx = 0.0f, sy = 0.0f;
    for (int n = grp; n < NN; n += ngrp) {
        float2 v = __half22float2(h[n * 32 + c]);
        sx += v.x; sy += v.y;
    }
    atomicAdd(&g_pool[2 * c], sx);
    atomicAdd(&g_pool[2 * c + 1], sy);
}

// ---------------- head: linear + log_softmax -> d_out [4,10] ---------------
__global__ void k_head(const float* __restrict__ lw, const float* __restrict__ lb,
                       float* __restrict__ out) {
    __shared__ float gsh[BF];
    __shared__ float lg[BB * CC];
    int tid = threadIdx.x;
    if (tid < BF) gsh[tid] = g_pool[tid] * (1.0f / (float)NN);
    __syncthreads();
    if (tid < BB * CC) {
        int b = tid / CC, c = tid % CC;
        float s = lb[c];
        #pragma unroll
        for (int hh = 0; hh < HH; hh++) s += gsh[b * HH + hh] * lw[c * HH + hh];
        lg[tid] = s;
    }
    __syncthreads();
    if (tid < BB * CC) {
        int b = tid / CC;
        float mx = -1e30f;
        for (int c2 = 0; c2 < CC; c2++) mx = fmaxf(mx, lg[b * CC + c2]);
        float se = 0.0f;
        for (int c2 = 0; c2 < CC; c2++) se += expf(lg[b * CC + c2] - mx);
        out[tid] = lg[tid] - mx - logf(se);
    }
}

// ---------------- launcher ----------------
extern "C" void kernel_launch(void* const* d_in, const int* in_sizes, int n_in,
                              void* d_out, int out_size) {
    const float* x  = (const float*)d_in[0];
    const int* ei   = (const int*)d_in[1];   // JAX x64 disabled -> int32
    const float* W1 = (const float*)d_in[2];
    const float* b1 = (const float*)d_in[3];
    const float* W2 = (const float*)d_in[4];
    const float* b2 = (const float*)d_in[5];
    const float* W3 = (const float*)d_in[6];
    const float* b3 = (const float*)d_in[7];
    const float* lw = (const float*)d_in[8];
    const float* lb = (const float*)d_in[9];
    float* out = (float*)d_out;

    __half *bufA, *bufAs, *bufB, *bufBs, *t1, *t2;
    cudaGetSymbolAddress((void**)&bufA, g_bufA);
    cudaGetSymbolAddress((void**)&bufAs, g_bufAs);
    cudaGetSymbolAddress((void**)&bufB, g_bufB);
    cudaGetSymbolAddress((void**)&bufBs, g_bufBs);
    cudaGetSymbolAddress((void**)&t1, g_t1);
    cudaGetSymbolAddress((void**)&t2, g_t2);

    const int EB = (EE + 255) / 256;
    const int PB = NN / 8;               // warp per node, 8 warps/block
    const int DB = (NN * BB + 255) / 256;
    const int SB2 = (NN * 8 + 255) / 256;

    dim3 tb(32, 8);
    dim3 tg((NN + 31) / 32, 2);
    k_transpose<<<tg, tb>>>(x, bufA);                            // 1
    k_fuse<<<EB, 256>>>(ei);                                     // 2
    k_dinvscale<<<SB2, 256>>>((const uint4*)bufA, (uint4*)bufAs);// 3

    // layer 1
    k_prop<<<PB, 256>>>(bufAs, t1);                              // 4 <- ncu window
    k_prop<<<PB, 256>>>(t1, t2);
    k_dense<1><<<DB, 256>>>(bufA, t1, t2, W1, b1, bufB, bufBs);
    // layer 2
    k_prop<<<PB, 256>>>(bufBs, t1);
    k_prop<<<PB, 256>>>(t1, t2);
    k_dense<1><<<DB, 256>>>(bufB, t1, t2, W2, b2, bufA, bufAs);
    // layer 3
    k_prop<<<PB, 256>>>(bufAs, t1);
    k_prop<<<PB, 256>>>(t1, t2);
    k_dense<0><<<DB, 256>>>(bufA, t1, t2, W3, b3, bufB, (__half*)nullptr);

    k_pool<<<256, 256>>>((const __half2*)bufB);
    k_head<<<1, 64>>>(lw, lb, out);
}

// round 14
// speedup vs baseline: 1.2558x; 1.2558x over previous
#include <cuda_runtime.h>
#include <cuda_fp16.h>
#include <cuda_fp8.h>
#include <math.h>

#define NN 50000
#define EE 1600000
#define BB 4
#define FF 16
#define HH 16
#define BF 64   // BB*FF values per node row
#define CC 10
#define CAP 96  // padded CSR bucket size
#define FSC 16.0f  // fp8 pre-scale

// ---------------- device scratch ----------------
__device__ uint4 g_bufA[NN * 8];    // z   (unscaled, fp16, 128B/row)
__device__ uint2 g_bufAs[NN * 8];   // FSC*dinv*z (fp8 e4m3, 64B/row)
__device__ uint4 g_bufB[NN * 8];
__device__ uint2 g_bufBs[NN * 8];
__device__ uint2 g_t1[NN * 8];      // scaled-domain prop1 out (fp8)
__device__ uint4 g_t2[NN * 8];      // scaled-domain prop2 out (fp16)
__device__ unsigned short g_csr[NN * CAP]; // bucket n at n*CAP: src (u16)
__device__ int   g_wp[NN];          // bucket fill = in-degree
__device__ int   g_deg[NN];         // out-degree
__device__ float g_dinv[NN];        // FSC * dinv
__device__ float g_dinv2[NN];       // true dinv^2
__device__ float g_rdinv[NN];       // sqrt(deg)/FSC
__device__ float g_pool[BF];

__device__ __forceinline__ float elu1(float x) {
    return x > 0.0f ? x : expm1f(x);
}
__device__ __forceinline__ __half2 fp8x2_to_h2(unsigned short u) {
    __half2_raw r = __nv_cvt_fp8x2_to_halfraw2((__nv_fp8x2_storage_t)u, __NV_E4M3);
    return *reinterpret_cast<__half2*>(&r);
}
__device__ __forceinline__ unsigned short f2_to_fp8x2(float x, float y) {
    float2 f; f.x = x; f.y = y;
    return (unsigned short)__nv_cvt_float2_to_fp8x2(f, __NV_SATFINITE, __NV_E4M3);
}
__device__ __forceinline__ unsigned short h2_to_fp8x2(__half2 h) {
    return (unsigned short)__nv_cvt_halfraw2_to_fp8x2(*reinterpret_cast<__half2_raw*>(&h),
                                                      __NV_SATFINITE, __NV_E4M3);
}

// ---------------- transpose x [B,F,N] fp32 -> [N,64] fp16 + init -----------
__global__ void k_transpose(const float* __restrict__ x, __half* __restrict__ dst) {
    int flat = (blockIdx.y * gridDim.x + blockIdx.x) * 256 + threadIdx.y * 32 + threadIdx.x;
    if (flat < NN) { g_wp[flat] = 0; g_deg[flat] = 0; }

    __shared__ float tile[32][33];
    int n0 = blockIdx.x * 32;
    int bf0 = blockIdx.y * 32;
    int tx = threadIdx.x;
    int ty = threadIdx.y;
    #pragma unroll
    for (int i = ty; i < 32; i += 8) {
        int n = n0 + tx;
        tile[i][tx] = (n < NN) ? x[(bf0 + i) * NN + n] : 0.0f;
    }
    __syncthreads();
    #pragma unroll
    for (int i = ty; i < 32; i += 8) {
        int n = n0 + i;
        if (n < NN) dst[n * BF + bf0 + tx] = __float2half_rn(tile[tx][i]);
    }
}

// ---------------- fused: deg RED + bucket scatter --------------------------
__global__ void k_fuse(const int* __restrict__ ei) {
    int e = blockIdx.x * 256 + threadIdx.x;
    if (e >= EE) return;
    int s = ei[e];
    int d = ei[EE + e];
    atomicAdd(&g_deg[s], 1);
    int pos = atomicAdd(&g_wp[d], 1);
    g_csr[d * CAP + pos] = (unsigned short)s;
}

// ---------------- dinv consts + scaled fp8 input buffer --------------------
__global__ void k_dinvscale(const uint4* __restrict__ z, uint2* __restrict__ zs) {
    int t = blockIdx.x * 256 + threadIdx.x;
    if (t < BF) g_pool[t] = 0.0f;
    if (t >= NN * 8) return;
    int n = t >> 3;
    int c = t & 7;
    int d = g_deg[n];
    float di = (d > 0) ? rsqrtf((float)d) : 0.0f;
    if (c == 0) {
        g_dinv[n] = FSC * di;
        g_dinv2[n] = di * di;
        g_rdinv[n] = (d > 0) ? (sqrtf((float)d) * (1.0f / FSC)) : 0.0f;
    }
    __half2 dh = __float2half2_rn(FSC * di);
    uint4 v = z[t];
    __half2 m0 = __hmul2(dh, *(__half2*)&v.x);
    __half2 m1 = __hmul2(dh, *(__half2*)&v.y);
    __half2 m2 = __hmul2(dh, *(__half2*)&v.z);
    __half2 m3 = __hmul2(dh, *(__half2*)&v.w);
    uint2 r;
    r.x = (unsigned)h2_to_fp8x2(m0) | ((unsigned)h2_to_fp8x2(m1) << 16);
    r.y = (unsigned)h2_to_fp8x2(m2) | ((unsigned)h2_to_fp8x2(m3) << 16);
    zs[t] = r;
}

// ---------------- sparse prop: fp8 gathered rows, weight-free sums ---------
// out_s[n,:] = -dinv2[n] * sum_{e->n} in_s[src_e,:]
// warp per dst node; 4 groups x 8 lanes; lane = 8B slice of the 64B fp8 row.
// OUT8: store fp8 (64B row) else fp16 (128B row).
template<int OUT8>
__global__ __launch_bounds__(256) void k_prop(const unsigned char* __restrict__ in,
                                              void* __restrict__ out) {
    int w = (blockIdx.x * 256 + threadIdx.x) >> 5;
    int lane = threadIdx.x & 31;
    if (w >= NN) return;
    int g = lane >> 3;             // edge-group 0..3
    int q = lane & 7;              // 8B slice 0..7
    const unsigned char* base = in + q * 8;
    int len = g_wp[w];
    int full = len >> 2;
    int rem = len & 3;

    const __half2 z2 = __float2half2_rn(0.0f);
    __half2 A0 = z2, A1 = z2, A2 = z2, A3 = z2;
    __half2 B0 = z2, B1 = z2, B2 = z2, B3 = z2;

    int j = w * CAP + g;
    int k = 0;
    #pragma unroll 2
    for (; k + 2 <= full; k += 2, j += 8) {
        unsigned s0 = __ldg(&g_csr[j]);
        unsigned s1 = __ldg(&g_csr[j + 4]);
        uint2 v0 = *(const uint2*)(base + s0 * 64);
        uint2 v1 = *(const uint2*)(base + s1 * 64);
        A0 = __hadd2(A0, fp8x2_to_h2((unsigned short)(v0.x)));
        A1 = __hadd2(A1, fp8x2_to_h2((unsigned short)(v0.x >> 16)));
        A2 = __hadd2(A2, fp8x2_to_h2((unsigned short)(v0.y)));
        A3 = __hadd2(A3, fp8x2_to_h2((unsigned short)(v0.y >> 16)));
        B0 = __hadd2(B0, fp8x2_to_h2((unsigned short)(v1.x)));
        B1 = __hadd2(B1, fp8x2_to_h2((unsigned short)(v1.x >> 16)));
        B2 = __hadd2(B2, fp8x2_to_h2((unsigned short)(v1.y)));
        B3 = __hadd2(B3, fp8x2_to_h2((unsigned short)(v1.y >> 16)));
    }
    if (k < full) {
        unsigned s0 = __ldg(&g_csr[j]);
        uint2 v = *(const uint2*)(base + s0 * 64);
        A0 = __hadd2(A0, fp8x2_to_h2((unsigned short)(v.x)));
        A1 = __hadd2(A1, fp8x2_to_h2((unsigned short)(v.x >> 16)));
        A2 = __hadd2(A2, fp8x2_to_h2((unsigned short)(v.y)));
        A3 = __hadd2(A3, fp8x2_to_h2((unsigned short)(v.y >> 16)));
        j += 4;
    }
    if (g < rem) {
        unsigned s0 = __ldg(&g_csr[j]);
        uint2 v = *(const uint2*)(base + s0 * 64);
        B0 = __hadd2(B0, fp8x2_to_h2((unsigned short)(v.x)));
        B1 = __hadd2(B1, fp8x2_to_h2((unsigned short)(v.x >> 16)));
        B2 = __hadd2(B2, fp8x2_to_h2((unsigned short)(v.y)));
        B3 = __hadd2(B3, fp8x2_to_h2((unsigned short)(v.y >> 16)));
    }

    float2 f0 = __half22float2(__hadd2(A0, B0));
    float2 f1 = __half22float2(__hadd2(A1, B1));
    float2 f2 = __half22float2(__hadd2(A2, B2));
    float2 f3 = __half22float2(__hadd2(A3, B3));
    float a0 = f0.x, a1 = f0.y, a2 = f1.x, a3 = f1.y;
    float a4 = f2.x, a5 = f2.y, a6 = f3.x, a7 = f3.y;

    a0 += __shfl_xor_sync(0xffffffffu, a0, 8);  a0 += __shfl_xor_sync(0xffffffffu, a0, 16);
    a1 += __shfl_xor_sync(0xffffffffu, a1, 8);  a1 += __shfl_xor_sync(0xffffffffu, a1, 16);
    a2 += __shfl_xor_sync(0xffffffffu, a2, 8);  a2 += __shfl_xor_sync(0xffffffffu, a2, 16);
    a3 += __shfl_xor_sync(0xffffffffu, a3, 8);  a3 += __shfl_xor_sync(0xffffffffu, a3, 16);
    a4 += __shfl_xor_sync(0xffffffffu, a4, 8);  a4 += __shfl_xor_sync(0xffffffffu, a4, 16);
    a5 += __shfl_xor_sync(0xffffffffu, a5, 8);  a5 += __shfl_xor_sync(0xffffffffu, a5, 16);
    a6 += __shfl_xor_sync(0xffffffffu, a6, 8);  a6 += __shfl_xor_sync(0xffffffffu, a6, 16);
    a7 += __shfl_xor_sync(0xffffffffu, a7, 8);  a7 += __shfl_xor_sync(0xffffffffu, a7, 16);

    if (g == 0) {
        float sc = -g_dinv2[w];
        if (OUT8) {
            uint2 r;
            r.x = (unsigned)f2_to_fp8x2(sc * a0, sc * a1)
                | ((unsigned)f2_to_fp8x2(sc * a2, sc * a3) << 16);
            r.y = (unsigned)f2_to_fp8x2(sc * a4, sc * a5)
                | ((unsigned)f2_to_fp8x2(sc * a6, sc * a7) << 16);
            *(uint2*)((unsigned char*)out + w * 64 + q * 8) = r;
        } else {
            __half2 h0 = __floats2half2_rn(sc * a0, sc * a1);
            __half2 h1 = __floats2half2_rn(sc * a2, sc * a3);
            __half2 h2 = __floats2half2_rn(sc * a4, sc * a5);
            __half2 h3 = __floats2half2_rn(sc * a6, sc * a7);
            uint4 r;
            r.x = *(unsigned*)&h0; r.y = *(unsigned*)&h1;
            r.z = *(unsigned*)&h2; r.w = *(unsigned*)&h3;
            *(uint4*)((char*)out + w * 128 + q * 16) = r;
        }
    }
}

// ---------------- dense ----------------------------------------------------
__device__ __forceinline__ void unpack8(uint4 v, float* a) {
    float2 f;
    f = __half22float2(*(__half2*)&v.x); a[0] = f.x; a[1] = f.y;
    f = __half22float2(*(__half2*)&v.y); a[2] = f.x; a[3] = f.y;
    f = __half22float2(*(__half2*)&v.z); a[4] = f.x; a[5] = f.y;
    f = __half22float2(*(__half2*)&v.w); a[6] = f.x; a[7] = f.y;
}
__device__ __forceinline__ void unpack8f8(unsigned lo, unsigned hi, float* a) {
    float2 f;
    f = __half22float2(fp8x2_to_h2((unsigned short)lo));         a[0] = f.x; a[1] = f.y;
    f = __half22float2(fp8x2_to_h2((unsigned short)(lo >> 16))); a[2] = f.x; a[3] = f.y;
    f = __half22float2(fp8x2_to_h2((unsigned short)hi));         a[4] = f.x; a[5] = f.y;
    f = __half22float2(fp8x2_to_h2((unsigned short)(hi >> 16))); a[6] = f.x; a[7] = f.y;
}

template<int WS>
__global__ __launch_bounds__(256) void k_dense(const __half* __restrict__ z,
                                               const unsigned char* __restrict__ t1s,
                                               const __half* __restrict__ t2s,
                                               const float* __restrict__ W,
                                               const float* __restrict__ bias,
                                               __half* __restrict__ out,
                                               unsigned char* __restrict__ outs) {
    __shared__ float sW[48 * 16];
    __shared__ float sB[16];
    int tid = threadIdx.x;
    for (int j = tid; j < 768; j += 256) {
        int kf = j >> 4;
        int o = j & 15;
        int k = kf >> 4;
        int f = kf & 15;
        sW[j] = W[k * 256 + o * 16 + f];
    }
    if (tid < 16) sB[tid] = bias[tid];
    __syncthreads();

    int r = blockIdx.x * 256 + tid;
    if (r >= NN * BB) return;
    int n = r >> 2;
    float rd = g_rdinv[n];

    float a[48];
    {
        const uint4* p0 = (const uint4*)(z + r * 16);
        uint4 q1 = *(const uint4*)(t1s + r * 16);   // 16 fp8
        const uint4* p2 = (const uint4*)(t2s + r * 16);
        unpack8(p0[0], a);      unpack8(p0[1], a + 8);
        unpack8f8(q1.x, q1.y, a + 16);
        unpack8f8(q1.z, q1.w, a + 24);
        unpack8(p2[0], a + 32); unpack8(p2[1], a + 40);
        float rd2 = 2.0f * rd;
        #pragma unroll
        for (int i = 0; i < 16; i++) {
            a[16 + i] *= rd;                          // Tx1 true
            a[32 + i] = fmaf(rd2, a[32 + i], -a[i]);  // 2*Tx2true - z
        }
    }
    float acc[16];
    #pragma unroll
    for (int o = 0; o < 16; o++) acc[o] = sB[o];
    #pragma unroll
    for (int kk = 0; kk < 48; kk++) {
        float av = a[kk];
        const float4* w4 = (const float4*)(sW + kk * 16);
        #pragma unroll
        for (int qq = 0; qq < 4; qq++) {
            float4 w = w4[qq];
            acc[qq * 4 + 0] = fmaf(av, w.x, acc[qq * 4 + 0]);
            acc[qq * 4 + 1] = fmaf(av, w.y, acc[qq * 4 + 1]);
            acc[qq * 4 + 2] = fmaf(av, w.z, acc[qq * 4 + 2]);
            acc[qq * 4 + 3] = fmaf(av, w.w, acc[qq * 4 + 3]);
        }
    }
    float h[16];
    #pragma unroll
    for (int i = 0; i < 16; i++) h[i] = elu1(acc[i]);

    uint4 o0, o1;
    {
        unsigned* po = (unsigned*)&o0;
        unsigned* po1 = (unsigned*)&o1;
        #pragma unroll
        for (int qq = 0; qq < 4; qq++) {
            __half2 hh = __floats2half2_rn(h[qq * 2 + 0], h[qq * 2 + 1]);
            po[qq] = *(unsigned*)&hh;
            __half2 hh2 = __floats2half2_rn(h[8 + qq * 2 + 0], h[8 + qq * 2 + 1]);
            po1[qq] = *(unsigned*)&hh2;
        }
    }
    uint4* dst = (uint4*)(out + r * 16);
    dst[0] = o0;
    dst[1] = o1;

    if (WS) {
        float di = g_dinv[n];    // = FSC * dinv
        uint4 s;
        s.x = (unsigned)f2_to_fp8x2(di * h[0],  di * h[1])
            | ((unsigned)f2_to_fp8x2(di * h[2],  di * h[3]) << 16);
        s.y = (unsigned)f2_to_fp8x2(di * h[4],  di * h[5])
            | ((unsigned)f2_to_fp8x2(di * h[6],  di * h[7]) << 16);
        s.z = (unsigned)f2_to_fp8x2(di * h[8],  di * h[9])
            | ((unsigned)f2_to_fp8x2(di * h[10], di * h[11]) << 16);
        s.w = (unsigned)f2_to_fp8x2(di * h[12], di * h[13])
            | ((unsigned)f2_to_fp8x2(di * h[14], di * h[15]) << 16);
        *(uint4*)(outs + r * 16) = s;
    }
}

// ---------------- mean pool (fp16 in, fp32 accum) --------------------------
__global__ void k_pool(const __half2* __restrict__ h) {
    int tid = blockIdx.x * blockDim.x + threadIdx.x;
    int c = tid & 31;
    int grp = tid >> 5;
    int ngrp = (gridDim.x * blockDim.x) >> 5;
    float sx = 0.0f, sy = 0.0f;
    for (int n = grp; n < NN; n += ngrp) {
        float2 v = __half22float2(h[n * 32 + c]);
        sx += v.x; sy += v.y;
    }
    atomicAdd(&g_pool[2 * c], sx);
    atomicAdd(&g_pool[2 * c + 1], sy);
}

// ---------------- head ----------------
__global__ void k_head(const float* __restrict__ lw, const float* __restrict__ lb,
                       float* __restrict__ out) {
    __shared__ float gsh[BF];
    __shared__ float lg[BB * CC];
    int tid = threadIdx.x;
    if (tid < BF) gsh[tid] = g_pool[tid] * (1.0f / (float)NN);
    __syncthreads();
    if (tid < BB * CC) {
        int b = tid / CC, c = tid % CC;
        float s = lb[c];
        #pragma unroll
        for (int hh = 0; hh < HH; hh++) s += gsh[b * HH + hh] * lw[c * HH + hh];
        lg[tid] = s;
    }
    __syncthreads();
    if (tid < BB * CC) {
        int b = tid / CC;
        float mx = -1e30f;
        for (int c2 = 0; c2 < CC; c2++) mx = fmaxf(mx, lg[b * CC + c2]);
        float se = 0.0f;
        for (int c2 = 0; c2 < CC; c2++) se += expf(lg[b * CC + c2] - mx);
        out[tid] = lg[tid] - mx - logf(se);
    }
}

// ---------------- launcher ----------------
extern "C" void kernel_launch(void* const* d_in, const int* in_sizes, int n_in,
                              void* d_out, int out_size) {
    const float* x  = (const float*)d_in[0];
    const int* ei   = (const int*)d_in[1];   // JAX x64 disabled -> int32
    const float* W1 = (const float*)d_in[2];
    const float* b1 = (const float*)d_in[3];
    const float* W2 = (const float*)d_in[4];
    const float* b2 = (const float*)d_in[5];
    const float* W3 = (const float*)d_in[6];
    const float* b3 = (const float*)d_in[7];
    const float* lw = (const float*)d_in[8];
    const float* lb = (const float*)d_in[9];
    float* out = (float*)d_out;

    __half *bufA, *bufB;
    unsigned char *bufAs, *bufBs, *t1;
    __half *t2;
    cudaGetSymbolAddress((void**)&bufA, g_bufA);
    cudaGetSymbolAddress((void**)&bufAs, g_bufAs);
    cudaGetSymbolAddress((void**)&bufB, g_bufB);
    cudaGetSymbolAddress((void**)&bufBs, g_bufBs);
    cudaGetSymbolAddress((void**)&t1, g_t1);
    cudaGetSymbolAddress((void**)&t2, g_t2);

    const int EB = (EE + 255) / 256;
    const int PB = NN / 8;
    const int DB = (NN * BB + 255) / 256;
    const int SB2 = (NN * 8 + 255) / 256;

    dim3 tb(32, 8);
    dim3 tg((NN + 31) / 32, 2);
    k_transpose<<<tg, tb>>>(x, bufA);                             // 1
    k_fuse<<<EB, 256>>>(ei);                                      // 2
    k_dinvscale<<<SB2, 256>>>((const uint4*)bufA, (uint2*)bufAs); // 3

    // layer 1
    k_prop<1><<<PB, 256>>>(bufAs, t1);                            // 4 <- ncu window
    k_prop<0><<<PB, 256>>>(t1, t2);
    k_dense<1><<<DB, 256>>>(bufA, t1, t2, W1, b1, bufB, bufBs);
    // layer 2
    k_prop<1><<<PB, 256>>>(bufBs, t1);
    k_prop<0><<<PB, 256>>>(t1, t2);
    k_dense<1><<<DB, 256>>>(bufB, t1, t2, W2, b2, bufA, bufAs);
    // layer 3
    k_prop<1><<<PB, 256>>>(bufAs, t1);
    k_prop<0><<<PB, 256>>>(t1, t2);
    k_dense<0><<<DB, 256>>>(bufA, t1, t2, W3, b3, bufB, (unsigned char*)nullptr);

    k_pool<<<256, 256>>>((const __half2*)bufB);
    k_head<<<1, 64>>>(lw, lb, out);
}

// round 15
// speedup vs baseline: 1.2909x; 1.0280x over previous
#include <cuda_runtime.h>
#include <cuda_fp16.h>
#include <cuda_fp8.h>
#include <math.h>

#define NN 50000
#define EE 1600000
#define BB 4
#define FF 16
#define HH 16
#define BF 64   // BB*FF values per node row
#define CC 10
#define CAP 96  // padded CSR bucket size
#define FSC 16.0f  // fp8 pre-scale

// ---------------- device scratch ----------------
__device__ uint4 g_bufA[NN * 8];    // z   (unscaled, fp16, 128B/row)
__device__ uint2 g_bufAs[NN * 8];   // FSC*dinv*z (fp8 e4m3, 64B/row)
__device__ uint4 g_bufB[NN * 8];
__device__ uint2 g_bufBs[NN * 8];
__device__ uint2 g_t1[NN * 8];      // scaled-domain prop1 out (fp8)
__device__ uint4 g_t2[NN * 8];      // scaled-domain prop2 out (fp16)
__device__ unsigned short g_csr[NN * CAP]; // bucket n at n*CAP: src (u16)
__device__ int   g_wp[NN];          // bucket fill = in-degree
__device__ int   g_deg[NN];         // out-degree
__device__ float g_dinv[NN];        // FSC * dinv
__device__ float g_dinv2[NN];       // true dinv^2
__device__ float g_rdinv[NN];       // sqrt(deg)/FSC
__device__ float g_pool[BF];

__device__ __forceinline__ float elu1(float x) {
    return x > 0.0f ? x : expm1f(x);
}
__device__ __forceinline__ __half2 fp8x2_to_h2(unsigned short u) {
    __half2_raw r = __nv_cvt_fp8x2_to_halfraw2((__nv_fp8x2_storage_t)u, __NV_E4M3);
    return *reinterpret_cast<__half2*>(&r);
}
__device__ __forceinline__ unsigned short f2_to_fp8x2(float x, float y) {
    float2 f; f.x = x; f.y = y;
    return (unsigned short)__nv_cvt_float2_to_fp8x2(f, __NV_SATFINITE, __NV_E4M3);
}
__device__ __forceinline__ unsigned short h2_to_fp8x2(__half2 h) {
    return (unsigned short)__nv_cvt_halfraw2_to_fp8x2(*reinterpret_cast<__half2_raw*>(&h),
                                                      __NV_SATFINITE, __NV_E4M3);
}
__device__ __forceinline__ __half2 shfl_xor_h2(__half2 v, int m) {
    unsigned u = __shfl_xor_sync(0xffffffffu, *reinterpret_cast<unsigned*>(&v), m);
    return *reinterpret_cast<__half2*>(&u);
}

// ---------------- transpose x [B,F,N] fp32 -> [N,64] fp16 + init -----------
__global__ void k_transpose(const float* __restrict__ x, __half* __restrict__ dst) {
    int flat = (blockIdx.y * gridDim.x + blockIdx.x) * 256 + threadIdx.y * 32 + threadIdx.x;
    if (flat < NN) { g_wp[flat] = 0; g_deg[flat] = 0; }

    __shared__ float tile[32][33];
    int n0 = blockIdx.x * 32;
    int bf0 = blockIdx.y * 32;
    int tx = threadIdx.x;
    int ty = threadIdx.y;
    #pragma unroll
    for (int i = ty; i < 32; i += 8) {
        int n = n0 + tx;
        tile[i][tx] = (n < NN) ? x[(bf0 + i) * NN + n] : 0.0f;
    }
    __syncthreads();
    #pragma unroll
    for (int i = ty; i < 32; i += 8) {
        int n = n0 + i;
        if (n < NN) dst[n * BF + bf0 + tx] = __float2half_rn(tile[tx][i]);
    }
}

// ---------------- fused: deg RED + bucket scatter --------------------------
__global__ void k_fuse(const int* __restrict__ ei) {
    int e = blockIdx.x * 256 + threadIdx.x;
    if (e >= EE) return;
    int s = ei[e];
    int d = ei[EE + e];
    atomicAdd(&g_deg[s], 1);
    int pos = atomicAdd(&g_wp[d], 1);
    g_csr[d * CAP + pos] = (unsigned short)s;
}

// ---------------- dinv consts + scaled fp8 input buffer --------------------
__global__ void k_dinvscale(const uint4* __restrict__ z, uint2* __restrict__ zs) {
    int t = blockIdx.x * 256 + threadIdx.x;
    if (t < BF) g_pool[t] = 0.0f;
    if (t >= NN * 8) return;
    int n = t >> 3;
    int c = t & 7;
    int d = g_deg[n];
    float di = (d > 0) ? rsqrtf((float)d) : 0.0f;
    if (c == 0) {
        g_dinv[n] = FSC * di;
        g_dinv2[n] = di * di;
        g_rdinv[n] = (d > 0) ? (sqrtf((float)d) * (1.0f / FSC)) : 0.0f;
    }
    __half2 dh = __float2half2_rn(FSC * di);
    uint4 v = z[t];
    __half2 m0 = __hmul2(dh, *(__half2*)&v.x);
    __half2 m1 = __hmul2(dh, *(__half2*)&v.y);
    __half2 m2 = __hmul2(dh, *(__half2*)&v.z);
    __half2 m3 = __hmul2(dh, *(__half2*)&v.w);
    uint2 r;
    r.x = (unsigned)h2_to_fp8x2(m0) | ((unsigned)h2_to_fp8x2(m1) << 16);
    r.y = (unsigned)h2_to_fp8x2(m2) | ((unsigned)h2_to_fp8x2(m3) << 16);
    zs[t] = r;
}

// ---------------- sparse prop: fp8 gathered rows, weight-free sums ---------
// out_s[n,:] = -dinv2[n] * sum_{e->n} in_s[src_e,:]
// warp per dst node; 4 groups x 8 lanes; lane = 8B slice of the 64B fp8 row.
// Epilogue entirely in half2 (packed shuffles, HMUL2 scale).
// OUT8: store fp8 (64B row) else fp16 (128B row).
template<int OUT8>
__global__ __launch_bounds__(256) void k_prop(const unsigned char* __restrict__ in,
                                              void* __restrict__ out) {
    int w = (blockIdx.x * 256 + threadIdx.x) >> 5;
    int lane = threadIdx.x & 31;
    if (w >= NN) return;
    int g = lane >> 3;             // edge-group 0..3
    int q = lane & 7;              // 8B slice 0..7
    const unsigned char* base = in + q * 8;
    int len = g_wp[w];
    int full = len >> 2;
    int rem = len & 3;

    const __half2 z2 = __float2half2_rn(0.0f);
    __half2 A0 = z2, A1 = z2, A2 = z2, A3 = z2;
    __half2 B0 = z2, B1 = z2, B2 = z2, B3 = z2;

    int j = w * CAP + g;
    int k = 0;
    #pragma unroll 2
    for (; k + 2 <= full; k += 2, j += 8) {
        unsigned s0 = __ldg(&g_csr[j]);
        unsigned s1 = __ldg(&g_csr[j + 4]);
        uint2 v0 = *(const uint2*)(base + s0 * 64);
        uint2 v1 = *(const uint2*)(base + s1 * 64);
        A0 = __hadd2(A0, fp8x2_to_h2((unsigned short)(v0.x)));
        A1 = __hadd2(A1, fp8x2_to_h2((unsigned short)(v0.x >> 16)));
        A2 = __hadd2(A2, fp8x2_to_h2((unsigned short)(v0.y)));
        A3 = __hadd2(A3, fp8x2_to_h2((unsigned short)(v0.y >> 16)));
        B0 = __hadd2(B0, fp8x2_to_h2((unsigned short)(v1.x)));
        B1 = __hadd2(B1, fp8x2_to_h2((unsigned short)(v1.x >> 16)));
        B2 = __hadd2(B2, fp8x2_to_h2((unsigned short)(v1.y)));
        B3 = __hadd2(B3, fp8x2_to_h2((unsigned short)(v1.y >> 16)));
    }
    if (k < full) {
        unsigned s0 = __ldg(&g_csr[j]);
        uint2 v = *(const uint2*)(base + s0 * 64);
        A0 = __hadd2(A0, fp8x2_to_h2((unsigned short)(v.x)));
        A1 = __hadd2(A1, fp8x2_to_h2((unsigned short)(v.x >> 16)));
        A2 = __hadd2(A2, fp8x2_to_h2((unsigned short)(v.y)));
        A3 = __hadd2(A3, fp8x2_to_h2((unsigned short)(v.y >> 16)));
        j += 4;
    }
    if (g < rem) {
        unsigned s0 = __ldg(&g_csr[j]);
        uint2 v = *(const uint2*)(base + s0 * 64);
        B0 = __hadd2(B0, fp8x2_to_h2((unsigned short)(v.x)));
        B1 = __hadd2(B1, fp8x2_to_h2((unsigned short)(v.x >> 16)));
        B2 = __hadd2(B2, fp8x2_to_h2((unsigned short)(v.y)));
        B3 = __hadd2(B3, fp8x2_to_h2((unsigned short)(v.y >> 16)));
    }

    // bank combine + cross-group reduce, all in half2
    __half2 S0 = __hadd2(A0, B0);
    __half2 S1 = __hadd2(A1, B1);
    __half2 S2 = __hadd2(A2, B2);
    __half2 S3 = __hadd2(A3, B3);
    S0 = __hadd2(S0, shfl_xor_h2(S0, 8));  S0 = __hadd2(S0, shfl_xor_h2(S0, 16));
    S1 = __hadd2(S1, shfl_xor_h2(S1, 8));  S1 = __hadd2(S1, shfl_xor_h2(S1, 16));
    S2 = __hadd2(S2, shfl_xor_h2(S2, 8));  S2 = __hadd2(S2, shfl_xor_h2(S2, 16));
    S3 = __hadd2(S3, shfl_xor_h2(S3, 8));  S3 = __hadd2(S3, shfl_xor_h2(S3, 16));

    if (g == 0) {
        __half2 sc = __float2half2_rn(-g_dinv2[w]);
        S0 = __hmul2(sc, S0);
        S1 = __hmul2(sc, S1);
        S2 = __hmul2(sc, S2);
        S3 = __hmul2(sc, S3);
        if (OUT8) {
            uint2 r;
            r.x = (unsigned)h2_to_fp8x2(S0) | ((unsigned)h2_to_fp8x2(S1) << 16);
            r.y = (unsigned)h2_to_fp8x2(S2) | ((unsigned)h2_to_fp8x2(S3) << 16);
            *(uint2*)((unsigned char*)out + w * 64 + q * 8) = r;
        } else {
            uint4 r;
            r.x = *(unsigned*)&S0; r.y = *(unsigned*)&S1;
            r.z = *(unsigned*)&S2; r.w = *(unsigned*)&S3;
            *(uint4*)((char*)out + w * 128 + q * 16) = r;
        }
    }
}

// ---------------- dense ----------------------------------------------------
__device__ __forceinline__ void unpack8(uint4 v, float* a) {
    float2 f;
    f = __half22float2(*(__half2*)&v.x); a[0] = f.x; a[1] = f.y;
    f = __half22float2(*(__half2*)&v.y); a[2] = f.x; a[3] = f.y;
    f = __half22float2(*(__half2*)&v.z); a[4] = f.x; a[5] = f.y;
    f = __half22float2(*(__half2*)&v.w); a[6] = f.x; a[7] = f.y;
}
__device__ __forceinline__ void unpack8f8(unsigned lo, unsigned hi, float* a) {
    float2 f;
    f = __half22float2(fp8x2_to_h2((unsigned short)lo));         a[0] = f.x; a[1] = f.y;
    f = __half22float2(fp8x2_to_h2((unsigned short)(lo >> 16))); a[2] = f.x; a[3] = f.y;
    f = __half22float2(fp8x2_to_h2((unsigned short)hi));         a[4] = f.x; a[5] = f.y;
    f = __half22float2(fp8x2_to_h2((unsigned short)(hi >> 16))); a[6] = f.x; a[7] = f.y;
}

template<int WS>
__global__ __launch_bounds__(256) void k_dense(const __half* __restrict__ z,
                                               const unsigned char* __restrict__ t1s,
                                               const __half* __restrict__ t2s,
                                               const float* __restrict__ W,
                                               const float* __restrict__ bias,
                                               __half* __restrict__ out,
                                               unsigned char* __restrict__ outs) {
    __shared__ float sW[48 * 16];
    __shared__ float sB[16];
    int tid = threadIdx.x;
    for (int j = tid; j < 768; j += 256) {
        int kf = j >> 4;
        int o = j & 15;
        int k = kf >> 4;
        int f = kf & 15;
        sW[j] = W[k * 256 + o * 16 + f];
    }
    if (tid < 16) sB[tid] = bias[tid];
    __syncthreads();

    int r = blockIdx.x * 256 + tid;
    if (r >= NN * BB) return;
    int n = r >> 2;
    float rd = g_rdinv[n];

    float a[48];
    {
        const uint4* p0 = (const uint4*)(z + r * 16);
        uint4 q1 = *(const uint4*)(t1s + r * 16);   // 16 fp8
        const uint4* p2 = (const uint4*)(t2s + r * 16);
        unpack8(p0[0], a);      unpack8(p0[1], a + 8);
        unpack8f8(q1.x, q1.y, a + 16);
        unpack8f8(q1.z, q1.w, a + 24);
        unpack8(p2[0], a + 32); unpack8(p2[1], a + 40);
        float rd2 = 2.0f * rd;
        #pragma unroll
        for (int i = 0; i < 16; i++) {
            a[16 + i] *= rd;                          // Tx1 true
            a[32 + i] = fmaf(rd2, a[32 + i], -a[i]);  // 2*Tx2true - z
        }
    }
    float acc[16];
    #pragma unroll
    for (int o = 0; o < 16; o++) acc[o] = sB[o];
    #pragma unroll
    for (int kk = 0; kk < 48; kk++) {
        float av = a[kk];
        const float4* w4 = (const float4*)(sW + kk * 16);
        #pragma unroll
        for (int qq = 0; qq < 4; qq++) {
            float4 w = w4[qq];
            acc[qq * 4 + 0] = fmaf(av, w.x, acc[qq * 4 + 0]);
            acc[qq * 4 + 1] = fmaf(av, w.y, acc[qq * 4 + 1]);
            acc[qq * 4 + 2] = fmaf(av, w.z, acc[qq * 4 + 2]);
            acc[qq * 4 + 3] = fmaf(av, w.w, acc[qq * 4 + 3]);
        }
    }
    float h[16];
    #pragma unroll
    for (int i = 0; i < 16; i++) h[i] = elu1(acc[i]);

    uint4 o0, o1;
    {
        unsigned* po = (unsigned*)&o0;
        unsigned* po1 = (unsigned*)&o1;
        #pragma unroll
        for (int qq = 0; qq < 4; qq++) {
            __half2 hh = __floats2half2_rn(h[qq * 2 + 0], h[qq * 2 + 1]);
            po[qq] = *(unsigned*)&hh;
            __half2 hh2 = __floats2half2_rn(h[8 + qq * 2 + 0], h[8 + qq * 2 + 1]);
            po1[qq] = *(unsigned*)&hh2;
        }
    }
    uint4* dst = (uint4*)(out + r * 16);
    dst[0] = o0;
    dst[1] = o1;

    if (WS) {
        float di = g_dinv[n];    // = FSC * dinv
        uint4 s;
        s.x = (unsigned)f2_to_fp8x2(di * h[0],  di * h[1])
            | ((unsigned)f2_to_fp8x2(di * h[2],  di * h[3]) << 16);
        s.y = (unsigned)f2_to_fp8x2(di * h[4],  di * h[5])
            | ((unsigned)f2_to_fp8x2(di * h[6],  di * h[7]) << 16);
        s.z = (unsigned)f2_to_fp8x2(di * h[8],  di * h[9])
            | ((unsigned)f2_to_fp8x2(di * h[10], di * h[11]) << 16);
        s.w = (unsigned)f2_to_fp8x2(di * h[12], di * h[13])
            | ((unsigned)f2_to_fp8x2(di * h[14], di * h[15]) << 16);
        *(uint4*)(outs + r * 16) = s;
    }
}

// ---------------- mean pool (fp16 in, fp32 accum) --------------------------
__global__ void k_pool(const __half2* __restrict__ h) {
    int tid = blockIdx.x * blockDim.x + threadIdx.x;
    int c = tid & 31;
    int grp = tid >> 5;
    int ngrp = (gridDim.x * blockDim.x) >> 5;
    float sx = 0.0f, sy = 0.0f;
    for (int n = grp; n < NN; n += ngrp) {
        float2 v = __half22float2(h[n * 32 + c]);
        sx += v.x; sy += v.y;
    }
    atomicAdd(&g_pool[2 * c], sx);
    atomicAdd(&g_pool[2 * c + 1], sy);
}

// ---------------- head ----------------
__global__ void k_head(const float* __restrict__ lw, const float* __restrict__ lb,
                       float* __restrict__ out) {
    __shared__ float gsh[BF];
    __shared__ float lg[BB * CC];
    int tid = threadIdx.x;
    if (tid < BF) gsh[tid] = g_pool[tid] * (1.0f / (float)NN);
    __syncthreads();
    if (tid < BB * CC) {
        int b = tid / CC, c = tid % CC;
        float s = lb[c];
        #pragma unroll
        for (int hh = 0; hh < HH; hh++) s += gsh[b * HH + hh] * lw[c * HH + hh];
        lg[tid] = s;
    }
    __syncthreads();
    if (tid < BB * CC) {
        int b = tid / CC;
        float mx = -1e30f;
        for (int c2 = 0; c2 < CC; c2++) mx = fmaxf(mx, lg[b * CC + c2]);
        float se = 0.0f;
        for (int c2 = 0; c2 < CC; c2++) se += expf(lg[b * CC + c2] - mx);
        out[tid] = lg[tid] - mx - logf(se);
    }
}

// ---------------- launcher ----------------
extern "C" void kernel_launch(void* const* d_in, const int* in_sizes, int n_in,
                              void* d_out, int out_size) {
    const float* x  = (const float*)d_in[0];
    const int* ei   = (const int*)d_in[1];   // JAX x64 disabled -> int32
    const float* W1 = (const float*)d_in[2];
    const float* b1 = (const float*)d_in[3];
    const float* W2 = (const float*)d_in[4];
    const float* b2 = (const float*)d_in[5];
    const float* W3 = (const float*)d_in[6];
    const float* b3 = (const float*)d_in[7];
    const float* lw = (const float*)d_in[8];
    const float* lb = (const float*)d_in[9];
    float* out = (float*)d_out;

    __half *bufA, *bufB;
    unsigned char *bufAs, *bufBs, *t1;
    __half *t2;
    cudaGetSymbolAddress((void**)&bufA, g_bufA);
    cudaGetSymbolAddress((void**)&bufAs, g_bufAs);
    cudaGetSymbolAddress((void**)&bufB, g_bufB);
    cudaGetSymbolAddress((void**)&bufBs, g_bufBs);
    cudaGetSymbolAddress((void**)&t1, g_t1);
    cudaGetSymbolAddress((void**)&t2, g_t2);

    const int EB = (EE + 255) / 256;
    const int PB = NN / 8;
    const int DB = (NN * BB + 255) / 256;
    const int SB2 = (NN * 8 + 255) / 256;

    dim3 tb(32, 8);
    dim3 tg((NN + 31) / 32, 2);
    k_transpose<<<tg, tb>>>(x, bufA);                             // 1
    k_fuse<<<EB, 256>>>(ei);                                      // 2
    k_dinvscale<<<SB2, 256>>>((const uint4*)bufA, (uint2*)bufAs); // 3

    // layer 1
    k_prop<1><<<PB, 256>>>(bufAs, t1);                            // 4 <- ncu window
    k_prop<0><<<PB, 256>>>(t1, t2);
    k_dense<1><<<DB, 256>>>(bufA, t1, t2, W1, b1, bufB, bufBs);
    // layer 2
    k_prop<1><<<PB, 256>>>(bufBs, t1);
    k_prop<0><<<PB, 256>>>(t1, t2);
    k_dense<1><<<DB, 256>>>(bufB, t1, t2, W2, b2, bufA, bufAs);
    // layer 3
    k_prop<1><<<PB, 256>>>(bufAs, t1);
    k_prop<0><<<PB, 256>>>(t1, t2);
    k_dense<0><<<DB, 256>>>(bufA, t1, t2, W3, b3, bufB, (unsigned char*)nullptr);

    k_pool<<<256, 256>>>((const __half2*)bufB);
    k_head<<<1, 64>>>(lw, lb, out);
}

// round 16
// speedup vs baseline: 1.3672x; 1.0591x over previous
#include <cuda_runtime.h>
#include <cuda_fp16.h>
#include <cuda_fp8.h>
#include <math.h>

#define NN 50000
#define EE 1600000
#define BB 4
#define FF 16
#define HH 16
#define BF 64   // BB*FF values per node row
#define CC 10
#define CAP 96  // padded CSR bucket size
#define FSC 16.0f  // fp8 pre-scale

// ---------------- device scratch ----------------
__device__ uint4 g_bufA[NN * 8];    // z   (unscaled, fp16, 128B/row)
__device__ uint2 g_bufAs[NN * 8];   // FSC*dinv*z (fp8 e4m3, 64B/row)
__device__ uint4 g_bufB[NN * 8];
__device__ uint2 g_bufBs[NN * 8];
__device__ uint2 g_t1[NN * 8];      // scaled-domain prop1 out (fp8)
__device__ uint4 g_t2[NN * 8];      // scaled-domain prop2 out (fp16)
__device__ unsigned short g_csr[NN * CAP + 32]; // +32 pad for index prefetch
__device__ int   g_wp[NN];          // bucket fill = in-degree
__device__ int   g_deg[NN];         // out-degree
__device__ float g_dinv[NN];        // FSC * dinv
__device__ float g_dinv2[NN];       // true dinv^2
__device__ float g_rdinv[NN];       // sqrt(deg)/FSC
__device__ float g_pool[BF];

__device__ __forceinline__ float elu1(float x) {
    return x > 0.0f ? x : expm1f(x);
}
__device__ __forceinline__ __half2 fp8x2_to_h2(unsigned short u) {
    __half2_raw r = __nv_cvt_fp8x2_to_halfraw2((__nv_fp8x2_storage_t)u, __NV_E4M3);
    return *reinterpret_cast<__half2*>(&r);
}
__device__ __forceinline__ unsigned short f2_to_fp8x2(float x, float y) {
    float2 f; f.x = x; f.y = y;
    return (unsigned short)__nv_cvt_float2_to_fp8x2(f, __NV_SATFINITE, __NV_E4M3);
}
__device__ __forceinline__ unsigned short h2_to_fp8x2(__half2 h) {
    return (unsigned short)__nv_cvt_halfraw2_to_fp8x2(*reinterpret_cast<__half2_raw*>(&h),
                                                      __NV_SATFINITE, __NV_E4M3);
}
__device__ __forceinline__ __half2 shfl_xor_h2(__half2 v, int m) {
    unsigned u = __shfl_xor_sync(0xffffffffu, *reinterpret_cast<unsigned*>(&v), m);
    return *reinterpret_cast<__half2*>(&u);
}

// ---------------- transpose x [B,F,N] fp32 -> [N,64] fp16 + init -----------
__global__ void k_transpose(const float* __restrict__ x, __half* __restrict__ dst) {
    int flat = (blockIdx.y * gridDim.x + blockIdx.x) * 256 + threadIdx.y * 32 + threadIdx.x;
    if (flat < NN) { g_wp[flat] = 0; g_deg[flat] = 0; }

    __shared__ float tile[32][33];
    int n0 = blockIdx.x * 32;
    int bf0 = blockIdx.y * 32;
    int tx = threadIdx.x;
    int ty = threadIdx.y;
    #pragma unroll
    for (int i = ty; i < 32; i += 8) {
        int n = n0 + tx;
        tile[i][tx] = (n < NN) ? x[(bf0 + i) * NN + n] : 0.0f;
    }
    __syncthreads();
    #pragma unroll
    for (int i = ty; i < 32; i += 8) {
        int n = n0 + i;
        if (n < NN) dst[n * BF + bf0 + tx] = __float2half_rn(tile[tx][i]);
    }
}

// ---------------- fused: deg RED + bucket scatter --------------------------
__global__ void k_fuse(const int* __restrict__ ei) {
    int e = blockIdx.x * 256 + threadIdx.x;
    if (e >= EE) return;
    int s = ei[e];
    int d = ei[EE + e];
    atomicAdd(&g_deg[s], 1);
    int pos = atomicAdd(&g_wp[d], 1);
    g_csr[d * CAP + pos] = (unsigned short)s;
}

// ---------------- dinv consts + scaled fp8 input buffer --------------------
__global__ void k_dinvscale(const uint4* __restrict__ z, uint2* __restrict__ zs) {
    int t = blockIdx.x * 256 + threadIdx.x;
    if (t < BF) g_pool[t] = 0.0f;
    if (t >= NN * 8) return;
    int n = t >> 3;
    int c = t & 7;
    int d = g_deg[n];
    float di = (d > 0) ? rsqrtf((float)d) : 0.0f;
    if (c == 0) {
        g_dinv[n] = FSC * di;
        g_dinv2[n] = di * di;
        g_rdinv[n] = (d > 0) ? (sqrtf((float)d) * (1.0f / FSC)) : 0.0f;
    }
    __half2 dh = __float2half2_rn(FSC * di);
    uint4 v = z[t];
    __half2 m0 = __hmul2(dh, *(__half2*)&v.x);
    __half2 m1 = __hmul2(dh, *(__half2*)&v.y);
    __half2 m2 = __hmul2(dh, *(__half2*)&v.z);
    __half2 m3 = __hmul2(dh, *(__half2*)&v.w);
    uint2 r;
    r.x = (unsigned)h2_to_fp8x2(m0) | ((unsigned)h2_to_fp8x2(m1) << 16);
    r.y = (unsigned)h2_to_fp8x2(m2) | ((unsigned)h2_to_fp8x2(m3) << 16);
    zs[t] = r;
}

// ---------------- sparse prop: fp8 gathered rows, weight-free sums ---------
// out_s[n,:] = -dinv2[n] * sum_{e->n} in_s[src_e,:]
// warp per dst node; 4 groups x 8 lanes; lane = 8B slice of the 64B fp8 row.
// Index PREFETCH: next iteration's csr indices load while current rows are
// in flight -> only one L2 latency exposed per iteration.
// OUT8: store fp8 (64B row) else fp16 (128B row).
template<int OUT8>
__global__ __launch_bounds__(256) void k_prop(const unsigned char* __restrict__ in,
                                              void* __restrict__ out) {
    int w = (blockIdx.x * 256 + threadIdx.x) >> 5;
    int lane = threadIdx.x & 31;
    if (w >= NN) return;
    int g = lane >> 3;             // edge-group 0..3
    int q = lane & 7;              // 8B slice 0..7
    const unsigned char* base = in + q * 8;
    int len = g_wp[w];
    float negd2 = -g_dinv2[w];     // hoisted
    int full = len >> 2;
    int rem = len & 3;

    const __half2 z2 = __float2half2_rn(0.0f);
    __half2 A0 = z2, A1 = z2, A2 = z2, A3 = z2;
    __half2 B0 = z2, B1 = z2, B2 = z2, B3 = z2;

    int j = w * CAP + g;
    unsigned s0 = __ldg(&g_csr[j]);        // pipeline prime
    unsigned s1 = __ldg(&g_csr[j + 4]);
    int k = 0;
    for (; k + 2 <= full; k += 2) {
        uint2 v0 = *(const uint2*)(base + s0 * 64);
        uint2 v1 = *(const uint2*)(base + s1 * 64);
        j += 8;
        s0 = __ldg(&g_csr[j]);             // prefetch next (padded; unused if loop exits)
        s1 = __ldg(&g_csr[j + 4]);
        A0 = __hadd2(A0, fp8x2_to_h2((unsigned short)(v0.x)));
        A1 = __hadd2(A1, fp8x2_to_h2((unsigned short)(v0.x >> 16)));
        A2 = __hadd2(A2, fp8x2_to_h2((unsigned short)(v0.y)));
        A3 = __hadd2(A3, fp8x2_to_h2((unsigned short)(v0.y >> 16)));
        B0 = __hadd2(B0, fp8x2_to_h2((unsigned short)(v1.x)));
        B1 = __hadd2(B1, fp8x2_to_h2((unsigned short)(v1.x >> 16)));
        B2 = __hadd2(B2, fp8x2_to_h2((unsigned short)(v1.y)));
        B3 = __hadd2(B3, fp8x2_to_h2((unsigned short)(v1.y >> 16)));
    }
    unsigned stail = s0;                   // csr[j] for the tail position
    if (k < full) {                        // one more full step: consume s0
        uint2 v = *(const uint2*)(base + s0 * 64);
        A0 = __hadd2(A0, fp8x2_to_h2((unsigned short)(v.x)));
        A1 = __hadd2(A1, fp8x2_to_h2((unsigned short)(v.x >> 16)));
        A2 = __hadd2(A2, fp8x2_to_h2((unsigned short)(v.y)));
        A3 = __hadd2(A3, fp8x2_to_h2((unsigned short)(v.y >> 16)));
        stail = s1;                        // s1 was loaded from j+4 = tail slot
    }
    if (g < rem) {
        uint2 v = *(const uint2*)(base + stail * 64);
        B0 = __hadd2(B0, fp8x2_to_h2((unsigned short)(v.x)));
        B1 = __hadd2(B1, fp8x2_to_h2((unsigned short)(v.x >> 16)));
        B2 = __hadd2(B2, fp8x2_to_h2((unsigned short)(v.y)));
        B3 = __hadd2(B3, fp8x2_to_h2((unsigned short)(v.y >> 16)));
    }

    // bank combine + cross-group reduce, all in half2
    __half2 S0 = __hadd2(A0, B0);
    __half2 S1 = __hadd2(A1, B1);
    __half2 S2 = __hadd2(A2, B2);
    __half2 S3 = __hadd2(A3, B3);
    S0 = __hadd2(S0, shfl_xor_h2(S0, 8));  S0 = __hadd2(S0, shfl_xor_h2(S0, 16));
    S1 = __hadd2(S1, shfl_xor_h2(S1, 8));  S1 = __hadd2(S1, shfl_xor_h2(S1, 16));
    S2 = __hadd2(S2, shfl_xor_h2(S2, 8));  S2 = __hadd2(S2, shfl_xor_h2(S2, 16));
    S3 = __hadd2(S3, shfl_xor_h2(S3, 8));  S3 = __hadd2(S3, shfl_xor_h2(S3, 16));

    if (g == 0) {
        __half2 sc = __float2half2_rn(negd2);
        S0 = __hmul2(sc, S0);
        S1 = __hmul2(sc, S1);
        S2 = __hmul2(sc, S2);
        S3 = __hmul2(sc, S3);
        if (OUT8) {
            uint2 r;
            r.x = (unsigned)h2_to_fp8x2(S0) | ((unsigned)h2_to_fp8x2(S1) << 16);
            r.y = (unsigned)h2_to_fp8x2(S2) | ((unsigned)h2_to_fp8x2(S3) << 16);
            *(uint2*)((unsigned char*)out + w * 64 + q * 8) = r;
        } else {
            uint4 r;
            r.x = *(unsigned*)&S0; r.y = *(unsigned*)&S1;
            r.z = *(unsigned*)&S2; r.w = *(unsigned*)&S3;
            *(uint4*)((char*)out + w * 128 + q * 16) = r;
        }
    }
}

// ---------------- dense ----------------------------------------------------
__device__ __forceinline__ void unpack8(uint4 v, float* a) {
    float2 f;
    f = __half22float2(*(__half2*)&v.x); a[0] = f.x; a[1] = f.y;
    f = __half22float2(*(__half2*)&v.y); a[2] = f.x; a[3] = f.y;
    f = __half22float2(*(__half2*)&v.z); a[4] = f.x; a[5] = f.y;
    f = __half22float2(*(__half2*)&v.w); a[6] = f.x; a[7] = f.y;
}
__device__ __forceinline__ void unpack8f8(unsigned lo, unsigned hi, float* a) {
    float2 f;
    f = __half22float2(fp8x2_to_h2((unsigned short)lo));         a[0] = f.x; a[1] = f.y;
    f = __half22float2(fp8x2_to_h2((unsigned short)(lo >> 16))); a[2] = f.x; a[3] = f.y;
    f = __half22float2(fp8x2_to_h2((unsigned short)hi));         a[4] = f.x; a[5] = f.y;
    f = __half22float2(fp8x2_to_h2((unsigned short)(hi >> 16))); a[6] = f.x; a[7] = f.y;
}

template<int WS>
__global__ __launch_bounds__(256) void k_dense(const __half* __restrict__ z,
                                               const unsigned char* __restrict__ t1s,
                                               const __half* __restrict__ t2s,
                                               const float* __restrict__ W,
                                               const float* __restrict__ bias,
                                               __half* __restrict__ out,
                                               unsigned char* __restrict__ outs) {
    __shared__ float sW[48 * 16];
    __shared__ float sB[16];
    int tid = threadIdx.x;
    for (int j = tid; j < 768; j += 256) {
        int kf = j >> 4;
        int o = j & 15;
        int k = kf >> 4;
        int f = kf & 15;
        sW[j] = W[k * 256 + o * 16 + f];
    }
    if (tid < 16) sB[tid] = bias[tid];
    __syncthreads();

    int r = blockIdx.x * 256 + tid;
    if (r >= NN * BB) return;
    int n = r >> 2;
    float rd = g_rdinv[n];

    float a[48];
    {
        const uint4* p0 = (const uint4*)(z + r * 16);
        uint4 q1 = *(const uint4*)(t1s + r * 16);   // 16 fp8
        const uint4* p2 = (const uint4*)(t2s + r * 16);
        unpack8(p0[0], a);      unpack8(p0[1], a + 8);
        unpack8f8(q1.x, q1.y, a + 16);
        unpack8f8(q1.z, q1.w, a + 24);
        unpack8(p2[0], a + 32); unpack8(p2[1], a + 40);
        float rd2 = 2.0f * rd;
        #pragma unroll
        for (int i = 0; i < 16; i++) {
            a[16 + i] *= rd;                          // Tx1 true
            a[32 + i] = fmaf(rd2, a[32 + i], -a[i]);  // 2*Tx2true - z
        }
    }
    float acc[16];
    #pragma unroll
    for (int o = 0; o < 16; o++) acc[o] = sB[o];
    #pragma unroll
    for (int kk = 0; kk < 48; kk++) {
        float av = a[kk];
        const float4* w4 = (const float4*)(sW + kk * 16);
        #pragma unroll
        for (int qq = 0; qq < 4; qq++) {
            float4 w = w4[qq];
            acc[qq * 4 + 0] = fmaf(av, w.x, acc[qq * 4 + 0]);
            acc[qq * 4 + 1] = fmaf(av, w.y, acc[qq * 4 + 1]);
            acc[qq * 4 + 2] = fmaf(av, w.z, acc[qq * 4 + 2]);
            acc[qq * 4 + 3] = fmaf(av, w.w, acc[qq * 4 + 3]);
        }
    }
    float h[16];
    #pragma unroll
    for (int i = 0; i < 16; i++) h[i] = elu1(acc[i]);

    uint4 o0, o1;
    {
        unsigned* po = (unsigned*)&o0;
        unsigned* po1 = (unsigned*)&o1;
        #pragma unroll
        for (int qq = 0; qq < 4; qq++) {
            __half2 hh = __floats2half2_rn(h[qq * 2 + 0], h[qq * 2 + 1]);
            po[qq] = *(unsigned*)&hh;
            __half2 hh2 = __floats2half2_rn(h[8 + qq * 2 + 0], h[8 + qq * 2 + 1]);
            po1[qq] = *(unsigned*)&hh2;
        }
    }
    uint4* dst = (uint4*)(out + r * 16);
    dst[0] = o0;
    dst[1] = o1;

    if (WS) {
        float di = g_dinv[n];    // = FSC * dinv
        uint4 s;
        s.x = (unsigned)f2_to_fp8x2(di * h[0],  di * h[1])
            | ((unsigned)f2_to_fp8x2(di * h[2],  di * h[3]) << 16);
        s.y = (unsigned)f2_to_fp8x2(di * h[4],  di * h[5])
            | ((unsigned)f2_to_fp8x2(di * h[6],  di * h[7]) << 16);
        s.z = (unsigned)f2_to_fp8x2(di * h[8],  di * h[9])
            | ((unsigned)f2_to_fp8x2(di * h[10], di * h[11]) << 16);
        s.w = (unsigned)f2_to_fp8x2(di * h[12], di * h[13])
            | ((unsigned)f2_to_fp8x2(di * h[14], di * h[15]) << 16);
        *(uint4*)(outs + r * 16) = s;
    }
}

// ---------------- mean pool (fp16 in, fp32 accum) --------------------------
__global__ void k_pool(const __half2* __restrict__ h) {
    int tid = blockIdx.x * blockDim.x + threadIdx.x;
    int c = tid & 31;
    int grp = tid >> 5;
    int ngrp = (gridDim.x * blockDim.x) >> 5;
    float sx = 0.0f, sy = 0.0f;
    for (int n = grp; n < NN; n += ngrp) {
        float2 v = __half22float2(h[n * 32 + c]);
        sx += v.x; sy += v.y;
    }
    atomicAdd(&g_pool[2 * c], sx);
    atomicAdd(&g_pool[2 * c + 1], sy);
}

// ---------------- head ----------------
__global__ void k_head(const float* __restrict__ lw, const float* __restrict__ lb,
                       float* __restrict__ out) {
    __shared__ float gsh[BF];
    __shared__ float lg[BB * CC];
    int tid = threadIdx.x;
    if (tid < BF) gsh[tid] = g_pool[tid] * (1.0f / (float)NN);
    __syncthreads();
    if (tid < BB * CC) {
        int b = tid / CC, c = tid % CC;
        float s = lb[c];
        #pragma unroll
        for (int hh = 0; hh < HH; hh++) s += gsh[b * HH + hh] * lw[c * HH + hh];
        lg[tid] = s;
    }
    __syncthreads();
    if (tid < BB * CC) {
        int b = tid / CC;
        float mx = -1e30f;
        for (int c2 = 0; c2 < CC; c2++) mx = fmaxf(mx, lg[b * CC + c2]);
        float se = 0.0f;
        for (int c2 = 0; c2 < CC; c2++) se += expf(lg[b * CC + c2] - mx);
        out[tid] = lg[tid] - mx - logf(se);
    }
}

// ---------------- launcher ----------------
extern "C" void kernel_launch(void* const* d_in, const int* in_sizes, int n_in,
                              void* d_out, int out_size) {
    const float* x  = (const float*)d_in[0];
    const int* ei   = (const int*)d_in[1];   // JAX x64 disabled -> int32
    const float* W1 = (const float*)d_in[2];
    const float* b1 = (const float*)d_in[3];
    const float* W2 = (const float*)d_in[4];
    const float* b2 = (const float*)d_in[5];
    const float* W3 = (const float*)d_in[6];
    const float* b3 = (const float*)d_in[7];
    const float* lw = (const float*)d_in[8];
    const float* lb = (const float*)d_in[9];
    float* out = (float*)d_out;

    __half *bufA, *bufB;
    unsigned char *bufAs, *bufBs, *t1;
    __half *t2;
    cudaGetSymbolAddress((void**)&bufA, g_bufA);
    cudaGetSymbolAddress((void**)&bufAs, g_bufAs);
    cudaGetSymbolAddress((void**)&bufB, g_bufB);
    cudaGetSymbolAddress((void**)&bufBs, g_bufBs);
    cudaGetSymbolAddress((void**)&t1, g_t1);
    cudaGetSymbolAddress((void**)&t2, g_t2);

    const int EB = (EE + 255) / 256;
    const int PB = NN / 8;
    const int DB = (NN * BB + 255) / 256;
    const int SB2 = (NN * 8 + 255) / 256;

    dim3 tb(32, 8);
    dim3 tg((NN + 31) / 32, 2);
    k_transpose<<<tg, tb>>>(x, bufA);                             // 1
    k_fuse<<<EB, 256>>>(ei);                                      // 2
    k_dinvscale<<<SB2, 256>>>((const uint4*)bufA, (uint2*)bufAs); // 3

    // layer 1
    k_prop<1><<<PB, 256>>>(bufAs, t1);                            // 4 <- ncu window
    k_prop<0><<<PB, 256>>>(t1, t2);
    k_dense<1><<<DB, 256>>>(bufA, t1, t2, W1, b1, bufB, bufBs);
    // layer 2
    k_prop<1><<<PB, 256>>>(bufBs, t1);
    k_prop<0><<<PB, 256>>>(t1, t2);
    k_dense<1><<<DB, 256>>>(bufB, t1, t2, W2, b2, bufA, bufAs);
    // layer 3
    k_prop<1><<<PB, 256>>>(bufAs, t1);
    k_prop<0><<<PB, 256>>>(t1, t2);
    k_dense<0><<<DB, 256>>>(bufA, t1, t2, W3, b3, bufB, (unsigned char*)nullptr);

    k_pool<<<256, 256>>>((const __half2*)bufB);
    k_head<<<1, 64>>>(lw, lb, out);
}